// round 5
// baseline (speedup 1.0000x reference)
#include <cuda_runtime.h>
#include <math.h>

#define NMAX 100000
#define EMAX 1600000
#define DIM 64

__device__ float g_hWa[(size_t)NMAX * DIM];
__device__ float g_hWb[(size_t)NMAX * DIM];
__device__ float g_pool[64 * DIM];
__device__ int   g_is64;
__device__ int   g_deg[NMAX];
__device__ int   g_off[NMAX + 1];
__device__ int   g_cursor[NMAX];
__device__ int   g_bsum[1024];
__device__ int   g_srcs[EMAX];

// ---------------------------------------------------------------------------
__global__ void detect_kernel(const int* __restrict__ e) {
    if (threadIdx.x == 0) {
        int all0 = 1;
        #pragma unroll
        for (int i = 1; i < 64; i += 2) all0 &= (e[i] == 0);
        g_is64 = all0;
    }
}

__global__ void zero_kernel(int M) {
    int t = blockIdx.x * blockDim.x + threadIdx.x;
    if (t < 64 * DIM) g_pool[t] = 0.0f;
    for (int i = t; i < M; i += blockDim.x * gridDim.x) g_deg[i] = 0;
}

// ---------------------------------------------------------------------------
// CSR build
__global__ __launch_bounds__(256) void hist_kernel(const void* __restrict__ eidx, int E) {
    int e = blockIdx.x * 256 + threadIdx.x;
    if (e >= E) return;
    int dst;
    if (g_is64) dst = (int)__ldg(&((const long long*)eidx)[E + e]);
    else        dst = __ldg(&((const int*)eidx)[E + e]);
    atomicAdd(&g_deg[dst], 1);
}

__global__ __launch_bounds__(256) void scan_local_kernel(int M) {
    __shared__ int warp_tot[8];
    __shared__ int wbase[8];
    const int t = threadIdx.x;
    const int idx0 = blockIdx.x * 1024 + t * 4;
    int v[4];
    #pragma unroll
    for (int i = 0; i < 4; i++) v[i] = (idx0 + i < M) ? g_deg[idx0 + i] : 0;
    int tot = v[0] + v[1] + v[2] + v[3];
    const int lane = t & 31, w = t >> 5;
    int sc = tot;
    #pragma unroll
    for (int o = 1; o < 32; o <<= 1) {
        int n = __shfl_up_sync(0xffffffffu, sc, o);
        if (lane >= o) sc += n;
    }
    if (lane == 31) warp_tot[w] = sc;
    __syncthreads();
    if (t == 0) {
        int s = 0;
        #pragma unroll
        for (int i = 0; i < 8; i++) { wbase[i] = s; s += warp_tot[i]; }
        g_bsum[blockIdx.x] = s;
    }
    __syncthreads();
    int run = sc - tot + wbase[w];
    #pragma unroll
    for (int i = 0; i < 4; i++) {
        if (idx0 + i < M) g_off[idx0 + i] = run;
        run += v[i];
    }
}

__global__ void scan_bsum_kernel(int nb) {
    if (threadIdx.x == 0) {
        int s = 0;
        for (int i = 0; i < nb; i++) { int v = g_bsum[i]; g_bsum[i] = s; s += v; }
    }
}

__global__ __launch_bounds__(256) void scan_add_kernel(int M, int E) {
    int i = blockIdx.x * 256 + threadIdx.x;
    if (i < M) {
        int o = g_off[i] + g_bsum[i >> 10];
        g_off[i] = o;
        g_cursor[i] = o;
    } else if (i == M) {
        g_off[M] = E;
    }
}

__global__ __launch_bounds__(256) void reorder_kernel(const void* __restrict__ eidx, int E) {
    int e = blockIdx.x * 256 + threadIdx.x;
    if (e >= E) return;
    int src, dst;
    if (g_is64) {
        const long long* p = (const long long*)eidx;
        src = (int)__ldg(&p[e]); dst = (int)__ldg(&p[E + e]);
    } else {
        const int* p = (const int*)eidx;
        src = __ldg(&p[e]); dst = __ldg(&p[E + e]);
    }
    int pos = atomicAdd(&g_cursor[dst], 1);
    g_srcs[pos] = src;
}

// ---------------------------------------------------------------------------
// Layer-0 first linear: hWa = X[M,128] @ W[128,64]
__global__ __launch_bounds__(256) void lin0_kernel(
    const float* __restrict__ X, const float* __restrict__ W, int M)
{
    extern __shared__ float sm[];
    float* Xs = sm;              // 64 x 132
    float* Ws = sm + 64 * 132;   // 128 x 64
    const int t = threadIdx.x;
    const int row0 = blockIdx.x * 64;

    {
        float4* wd = (float4*)Ws;
        const float4* ws = (const float4*)W;
        for (int i = t; i < 128 * 16; i += 256) wd[i] = ws[i];
    }
    for (int i = t; i < 64 * 32; i += 256) {
        int r = i >> 5, kk = i & 31;
        int gr = row0 + r; if (gr >= M) gr = M - 1;
        float4 v = *(const float4*)(X + (size_t)gr * 128 + kk * 4);
        *(float4*)(Xs + r * 132 + kk * 4) = v;
    }
    __syncthreads();

    const int tc = (t & 15) * 4;
    const int tr = (t >> 4) * 4;
    float acc[4][4] = {};
    #pragma unroll 4
    for (int k = 0; k < 128; k++) {
        float4 w = *(const float4*)(Ws + k * 64 + tc);
        #pragma unroll
        for (int i = 0; i < 4; i++) {
            float x = Xs[(tr + i) * 132 + k];
            acc[i][0] += x * w.x; acc[i][1] += x * w.y;
            acc[i][2] += x * w.z; acc[i][3] += x * w.w;
        }
    }
    #pragma unroll
    for (int i = 0; i < 4; i++) {
        int gr = row0 + tr + i;
        if (gr < M) {
            float4 v = make_float4(acc[i][0], acc[i][1], acc[i][2], acc[i][3]);
            *(float4*)(g_hWa + (size_t)gr * DIM + tc) = v;
        }
    }
}

// ---------------------------------------------------------------------------
// Fused layer: gather (from IN buffer) + BN-affine+ReLU + GEMM1(+bias,ReLU)
// + [GEMM2 -> OUT buffer | pooling]. Double-buffered hW to avoid the
// read/write race between gather and GEMM2 across blocks.
template <bool NEXT>
__global__ __launch_bounds__(256, 3) void layer_kernel(
    const float* __restrict__ IN, float* __restrict__ OUT,
    const float* __restrict__ ba, const float* __restrict__ gam,
    const float* __restrict__ bet, const float* __restrict__ Wb,
    const float* __restrict__ bb, const float* __restrict__ Wn,
    const void* __restrict__ batchp, int M)
{
    extern __shared__ float sm[];
    float* zs  = sm;                 // 64 x 68 (z, later overwritten with h)
    float* Wbs = zs + 64 * 68;       // 64 x 64
    float* Wns = Wbs + 64 * 64;      // 64 x 64 (NEXT only)
    __shared__ float A[64], B[64], bbs[64];
    __shared__ int sbat[64];

    const int t = threadIdx.x;
    const int row0 = blockIdx.x * 64;

    if (t < 64) {
        float inv = rsqrtf(1.0f + 1e-5f);
        float a = gam[t] * inv;
        A[t] = a;
        B[t] = ba[t] * a + bet[t];
        bbs[t] = bb[t];
    }
    {
        float4* wd = (float4*)Wbs;
        const float4* ws = (const float4*)Wb;
        for (int i = t; i < 1024; i += 256) wd[i] = ws[i];
        if (NEXT) {
            float4* nd = (float4*)Wns;
            const float4* ns = (const float4*)Wn;
            for (int i = t; i < 1024; i += 256) nd[i] = ns[i];
        }
    }
    __syncthreads();   // A/B ready before gather stores

    // ---- gather phase: warp w owns rows w*8 .. w*8+7 of this tile ----
    {
        const int w = t >> 5, lane = t & 31;
        const int h = lane >> 4, j = lane & 15;
        #pragma unroll
        for (int rr = 0; rr < 8; rr++) {
            const int r = w * 8 + rr;
            const int gr = row0 + r;
            if (gr < M) {
                const int beg = g_off[gr], end = g_off[gr + 1];
                float4 acc = make_float4(0.f, 0.f, 0.f, 0.f);
                for (int k = beg + h; k < end; k += 2) {
                    int s = __ldg(&g_srcs[k]);
                    float4 v = __ldg((const float4*)(IN + (size_t)s * DIM) + j);
                    acc.x += v.x; acc.y += v.y; acc.z += v.z; acc.w += v.w;
                }
                acc.x += __shfl_down_sync(0xffffffffu, acc.x, 16);
                acc.y += __shfl_down_sync(0xffffffffu, acc.y, 16);
                acc.z += __shfl_down_sync(0xffffffffu, acc.z, 16);
                acc.w += __shfl_down_sync(0xffffffffu, acc.w, 16);
                if (h == 0) {
                    float4 self = __ldg((const float4*)(IN + (size_t)gr * DIM) + j);
                    int c = j * 4;
                    float4 z;
                    z.x = fmaxf((acc.x + self.x) * A[c + 0] + B[c + 0], 0.0f);
                    z.y = fmaxf((acc.y + self.y) * A[c + 1] + B[c + 1], 0.0f);
                    z.z = fmaxf((acc.z + self.z) * A[c + 2] + B[c + 2], 0.0f);
                    z.w = fmaxf((acc.w + self.w) * A[c + 3] + B[c + 3], 0.0f);
                    *(float4*)(zs + r * 68 + c) = z;
                }
            } else if (h == 0) {
                *(float4*)(zs + r * 68 + j * 4) = make_float4(0.f, 0.f, 0.f, 0.f);
            }
        }
    }
    __syncthreads();

    const int tc = (t & 15) * 4;
    const int tr = (t >> 4) * 4;

    // ---- GEMM1: h = relu(z @ Wb + bb), result staged in registers ----
    float hreg[4][4];
    {
        float acc[4][4] = {};
        #pragma unroll 4
        for (int k = 0; k < 64; k++) {
            float4 w = *(const float4*)(Wbs + k * 64 + tc);
            #pragma unroll
            for (int i = 0; i < 4; i++) {
                float x = zs[(tr + i) * 68 + k];
                acc[i][0] += x * w.x; acc[i][1] += x * w.y;
                acc[i][2] += x * w.z; acc[i][3] += x * w.w;
            }
        }
        #pragma unroll
        for (int i = 0; i < 4; i++) {
            hreg[i][0] = fmaxf(acc[i][0] + bbs[tc + 0], 0.0f);
            hreg[i][1] = fmaxf(acc[i][1] + bbs[tc + 1], 0.0f);
            hreg[i][2] = fmaxf(acc[i][2] + bbs[tc + 2], 0.0f);
            hreg[i][3] = fmaxf(acc[i][3] + bbs[tc + 3], 0.0f);
        }
    }
    __syncthreads();   // all reads of z done
    #pragma unroll
    for (int i = 0; i < 4; i++)
        *(float4*)(zs + (tr + i) * 68 + tc) =
            make_float4(hreg[i][0], hreg[i][1], hreg[i][2], hreg[i][3]);
    __syncthreads();   // h fully in smem

    if (NEXT) {
        // ---- GEMM2: hW' = h @ Wn -> OUT ----
        float acc[4][4] = {};
        #pragma unroll 4
        for (int k = 0; k < 64; k++) {
            float4 w = *(const float4*)(Wns + k * 64 + tc);
            #pragma unroll
            for (int i = 0; i < 4; i++) {
                float x = zs[(tr + i) * 68 + k];
                acc[i][0] += x * w.x; acc[i][1] += x * w.y;
                acc[i][2] += x * w.z; acc[i][3] += x * w.w;
            }
        }
        #pragma unroll
        for (int i = 0; i < 4; i++) {
            int gr = row0 + tr + i;
            if (gr < M) {
                float4 v = make_float4(acc[i][0], acc[i][1], acc[i][2], acc[i][3]);
                *(float4*)(OUT + (size_t)gr * DIM + tc) = v;
            }
        }
    } else {
        // ---- pooling: batch sorted -> run-length reduce per column ----
        if (t < 64) {
            int gr = row0 + t;
            int b = -1;
            if (gr < M) {
                if (g_is64) b = (int)((const long long*)batchp)[gr];
                else        b = ((const int*)batchp)[gr];
            }
            sbat[t] = b;
        }
        __syncthreads();
        if (t < 64) {
            const int c = t;
            float s = 0.0f;
            int cur = sbat[0];
            for (int r = 0; r < 64; r++) {
                int b = sbat[r];
                if (b < 0) break;
                if (b != cur) {
                    atomicAdd(&g_pool[cur * DIM + c], s);
                    s = 0.0f; cur = b;
                }
                s += zs[r * 68 + c];
            }
            if (cur >= 0) atomicAdd(&g_pool[cur * DIM + c], s);
        }
    }
}

// ---------------------------------------------------------------------------
__global__ __launch_bounds__(256) void cls_kernel(
    const float* __restrict__ Wl1, const float* __restrict__ bl1,
    const float* __restrict__ Wl2, const float* __restrict__ bl2,
    float* __restrict__ out)
{
    extern __shared__ float sm[];
    float* ps  = sm;             // 64 x 64 pooled
    float* Ws1 = ps + 4096;      // 64 x 64 summed Wl1
    float* z1  = Ws1 + 4096;     // 64 x 65
    const int t = threadIdx.x;

    for (int i = t; i < 4096; i += 256) {
        ps[i]  = g_pool[i];
        Ws1[i] = Wl1[i] + Wl1[4096 + i] + Wl1[8192 + i];
    }
    __syncthreads();

    const int c = t & 63;
    const int gbase = (t >> 6) * 16;
    for (int gg = 0; gg < 16; gg++) {
        int g = gbase + gg;
        float s = bl1[c];
        #pragma unroll 8
        for (int k = 0; k < 64; k++) s += ps[g * 64 + k] * Ws1[k * 64 + c];
        z1[g * 65 + c] = fmaxf(s, 0.0f);
    }
    __syncthreads();

    if (t < 64) {
        const int g = t;
        float a = bl2[0], b = bl2[1];
        #pragma unroll 8
        for (int k = 0; k < 64; k++) {
            float v = z1[g * 65 + k];
            a += v * Wl2[k * 2 + 0];
            b += v * Wl2[k * 2 + 1];
        }
        float m = fmaxf(a, b);
        float l = m + logf(expf(a - m) + expf(b - m));
        out[2 * g + 0] = a - l;
        out[2 * g + 1] = b - l;
    }
}

// ---------------------------------------------------------------------------
extern "C" void kernel_launch(void* const* d_in, const int* in_sizes, int n_in,
                              void* d_out, int out_size)
{
    const float* x     = (const float*)d_in[0];
    const void*  eidx  = d_in[1];
    const void*  batch = d_in[2];
    const float* W0a   = (const float*)d_in[3];
    const float* b0a   = (const float*)d_in[4];
    const float* g0    = (const float*)d_in[5];
    const float* be0   = (const float*)d_in[6];
    const float* W0b   = (const float*)d_in[7];
    const float* b0b   = (const float*)d_in[8];
    const float* Wsa   = (const float*)d_in[9];
    const float* bsa   = (const float*)d_in[10];
    const float* gs    = (const float*)d_in[11];
    const float* bes   = (const float*)d_in[12];
    const float* Wsb   = (const float*)d_in[13];
    const float* bsb   = (const float*)d_in[14];
    const float* Wl1   = (const float*)d_in[15];
    const float* bl1   = (const float*)d_in[16];
    const float* Wl2   = (const float*)d_in[17];
    const float* bl2   = (const float*)d_in[18];

    const int M = in_sizes[0] / 128;
    const int E = in_sizes[1] / 2;
    const int nblk = (M + 63) / 64;
    const int eblk = (E + 255) / 256;
    const int sblk = (M + 1023) / 1024;

    const size_t smem_lin0  = (64 * 132 + 128 * 64) * sizeof(float);   // 66560
    const size_t smem_layer = (64 * 68 + 4096 * 2) * sizeof(float);    // 50176
    const size_t smem_cls   = (4096 + 4096 + 64 * 65) * sizeof(float);

    cudaFuncSetAttribute(lin0_kernel, cudaFuncAttributeMaxDynamicSharedMemorySize, (int)smem_lin0);
    cudaFuncSetAttribute(layer_kernel<true>, cudaFuncAttributeMaxDynamicSharedMemorySize, (int)smem_layer);
    cudaFuncSetAttribute(layer_kernel<false>, cudaFuncAttributeMaxDynamicSharedMemorySize, (int)smem_layer);
    cudaFuncSetAttribute(cls_kernel, cudaFuncAttributeMaxDynamicSharedMemorySize, (int)smem_cls);

    float* hWa = nullptr; float* hWb = nullptr;
    cudaGetSymbolAddress((void**)&hWa, g_hWa);
    cudaGetSymbolAddress((void**)&hWb, g_hWb);

    detect_kernel<<<1, 32>>>((const int*)eidx);
    zero_kernel<<<64, 256>>>(M);

    // build dst-CSR once; reused by all 3 layers
    hist_kernel<<<eblk, 256>>>(eidx, E);
    scan_local_kernel<<<sblk, 256>>>(M);
    scan_bsum_kernel<<<1, 32>>>(sblk);
    scan_add_kernel<<<(M + 256) / 256 + 1, 256>>>(M, E);
    reorder_kernel<<<eblk, 256>>>(eidx, E);

    lin0_kernel<<<nblk, 256, smem_lin0>>>(x, W0a, M);
    // layer0: read hWa -> write hWb
    layer_kernel<true><<<nblk, 256, smem_layer>>>(hWa, hWb,
        b0a, g0, be0, W0b, b0b, Wsa, nullptr, M);
    // layer1: read hWb -> write hWa
    layer_kernel<true><<<nblk, 256, smem_layer>>>(hWb, hWa,
        bsa, gs, bes, Wsb, bsb, Wsa + 4096, nullptr, M);
    // layer2: read hWa -> pooling
    layer_kernel<false><<<nblk, 256, smem_layer>>>(hWa, nullptr,
        bsa + 64, gs + 64, bes + 64, Wsb + 4096, bsb + 64, nullptr, batch, M);
    cls_kernel<<<1, 256, smem_cls>>>(Wl1, bl1, Wl2, bl2, (float*)d_out);
}

// round 6
// speedup vs baseline: 1.3654x; 1.3654x over previous
#include <cuda_runtime.h>
#include <math.h>
#include <stdint.h>

#define NMAX 100000
#define EMAX 1600000
#define DIM 64

__device__ float g_hW[(size_t)NMAX * DIM];
__device__ float g_acc[(size_t)NMAX * DIM];
__device__ float g_pool[64 * DIM];
__device__ int   g_is64;
__device__ int   g_deg[NMAX];
__device__ int   g_off[NMAX + 1];
__device__ int   g_cursor[NMAX];
__device__ int   g_bsum[1024];
__device__ int   g_srcs[EMAX];

// ---------------------------------------------------------------------------
__device__ __forceinline__ float to_tf32(float x) {
    uint32_t u;
    asm("cvt.rna.tf32.f32 %0, %1;" : "=r"(u) : "f"(x));
    return __uint_as_float(u);
}

__device__ __forceinline__ void mma_tf32(float* c, uint32_t a0, uint32_t a1,
                                         uint32_t a2, uint32_t a3,
                                         uint32_t b0, uint32_t b1) {
    asm volatile(
        "mma.sync.aligned.m16n8k8.row.col.f32.tf32.tf32.f32 "
        "{%0,%1,%2,%3}, {%4,%5,%6,%7}, {%8,%9}, {%0,%1,%2,%3};"
        : "+f"(c[0]), "+f"(c[1]), "+f"(c[2]), "+f"(c[3])
        : "r"(a0), "r"(a1), "r"(a2), "r"(a3), "r"(b0), "r"(b1));
}

// ---------------------------------------------------------------------------
__global__ void detect_kernel(const int* __restrict__ e) {
    if (threadIdx.x == 0) {
        int all0 = 1;
        #pragma unroll
        for (int i = 1; i < 64; i += 2) all0 &= (e[i] == 0);
        g_is64 = all0;
    }
}

__global__ void zero_kernel(int M) {
    int t = blockIdx.x * blockDim.x + threadIdx.x;
    if (t < 64 * DIM) g_pool[t] = 0.0f;
    for (int i = t; i < M; i += blockDim.x * gridDim.x) g_deg[i] = 0;
}

// ---------------------------------------------------------------------------
// CSR build
__global__ __launch_bounds__(256) void hist_kernel(const void* __restrict__ eidx, int E) {
    int e = blockIdx.x * 256 + threadIdx.x;
    if (e >= E) return;
    int dst;
    if (g_is64) dst = (int)__ldg(&((const long long*)eidx)[E + e]);
    else        dst = __ldg(&((const int*)eidx)[E + e]);
    atomicAdd(&g_deg[dst], 1);
}

__global__ __launch_bounds__(256) void scan_local_kernel(int M) {
    __shared__ int warp_tot[8];
    __shared__ int wbase[8];
    const int t = threadIdx.x;
    const int idx0 = blockIdx.x * 1024 + t * 4;
    int v[4];
    #pragma unroll
    for (int i = 0; i < 4; i++) v[i] = (idx0 + i < M) ? g_deg[idx0 + i] : 0;
    int tot = v[0] + v[1] + v[2] + v[3];
    const int lane = t & 31, w = t >> 5;
    int sc = tot;
    #pragma unroll
    for (int o = 1; o < 32; o <<= 1) {
        int n = __shfl_up_sync(0xffffffffu, sc, o);
        if (lane >= o) sc += n;
    }
    if (lane == 31) warp_tot[w] = sc;
    __syncthreads();
    if (t == 0) {
        int s = 0;
        #pragma unroll
        for (int i = 0; i < 8; i++) { wbase[i] = s; s += warp_tot[i]; }
        g_bsum[blockIdx.x] = s;
    }
    __syncthreads();
    int run = sc - tot + wbase[w];
    #pragma unroll
    for (int i = 0; i < 4; i++) {
        if (idx0 + i < M) g_off[idx0 + i] = run;
        run += v[i];
    }
}

__global__ void scan_bsum_kernel(int nb) {
    if (threadIdx.x == 0) {
        int s = 0;
        for (int i = 0; i < nb; i++) { int v = g_bsum[i]; g_bsum[i] = s; s += v; }
    }
}

__global__ __launch_bounds__(256) void scan_add_kernel(int M, int E) {
    int i = blockIdx.x * 256 + threadIdx.x;
    if (i < M) {
        int o = g_off[i] + g_bsum[i >> 10];
        g_off[i] = o;
        g_cursor[i] = o;
    } else if (i == M) {
        g_off[M] = E;
    }
}

__global__ __launch_bounds__(256) void reorder_kernel(const void* __restrict__ eidx, int E) {
    int e = blockIdx.x * 256 + threadIdx.x;
    if (e >= E) return;
    int src, dst;
    if (g_is64) {
        const long long* p = (const long long*)eidx;
        src = (int)__ldg(&p[e]); dst = (int)__ldg(&p[E + e]);
    } else {
        const int* p = (const int*)eidx;
        src = __ldg(&p[e]); dst = __ldg(&p[E + e]);
    }
    int pos = atomicAdd(&g_cursor[dst], 1);
    g_srcs[pos] = src;
}

// ---------------------------------------------------------------------------
// Gather: one warp per dst node (R4 layout — high occupancy, L2-roofline bound)
__global__ __launch_bounds__(256) void gather_kernel(int M) {
    const int warp = (blockIdx.x * 256 + threadIdx.x) >> 5;
    if (warp >= M) return;
    const int lane = threadIdx.x & 31;
    const int h = lane >> 4;
    const int j = lane & 15;

    const int beg = g_off[warp], end = g_off[warp + 1];
    float4 acc = make_float4(0.f, 0.f, 0.f, 0.f);
    for (int k = beg + h; k < end; k += 2) {
        int s = __ldg(&g_srcs[k]);
        float4 v = __ldg((const float4*)(g_hW + (size_t)s * DIM) + j);
        acc.x += v.x; acc.y += v.y; acc.z += v.z; acc.w += v.w;
    }
    acc.x += __shfl_down_sync(0xffffffffu, acc.x, 16);
    acc.y += __shfl_down_sync(0xffffffffu, acc.y, 16);
    acc.z += __shfl_down_sync(0xffffffffu, acc.z, 16);
    acc.w += __shfl_down_sync(0xffffffffu, acc.w, 16);
    if (h == 0) {
        float4 self = __ldg((const float4*)(g_hW + (size_t)warp * DIM) + j);
        acc.x += self.x; acc.y += self.y; acc.z += self.z; acc.w += self.w;
        *((float4*)(g_acc + (size_t)warp * DIM) + j) = acc;
    }
}

// ---------------------------------------------------------------------------
// Layer-0 first linear: hW = X[M,128] @ W[128,64], tf32 tensor cores.
__global__ __launch_bounds__(256) void lin0_kernel(
    const float* __restrict__ X, const float* __restrict__ W, int M)
{
    extern __shared__ float sm[];
    float* Xs = sm;                // 64 x 132 (tf32)
    float* Ws = sm + 64 * 132;     // 128 x 72 (tf32)
    const int t = threadIdx.x;
    const int row0 = blockIdx.x * 64;

    // load + convert W (128x64) into stride-72 smem
    for (int i = t; i < 128 * 16; i += 256) {
        int k = i >> 4, q = i & 15;
        float4 v = *(const float4*)(W + k * 64 + q * 4);
        v.x = to_tf32(v.x); v.y = to_tf32(v.y); v.z = to_tf32(v.z); v.w = to_tf32(v.w);
        *(float4*)(Ws + k * 72 + q * 4) = v;
    }
    // load + convert X tile
    for (int i = t; i < 64 * 32; i += 256) {
        int r = i >> 5, kk = i & 31;
        int gr = row0 + r; if (gr >= M) gr = M - 1;
        float4 v = *(const float4*)(X + (size_t)gr * 128 + kk * 4);
        v.x = to_tf32(v.x); v.y = to_tf32(v.y); v.z = to_tf32(v.z); v.w = to_tf32(v.w);
        *(float4*)(Xs + r * 132 + kk * 4) = v;
    }
    __syncthreads();

    const int w = t >> 5, lane = t & 31;
    const int gid = lane >> 2, tig = lane & 3;
    const int rows0 = (w >> 1) * 16;
    const int cols0 = (w & 1) * 32;

    float c[4][4] = {};
    #pragma unroll
    for (int k0 = 0; k0 < 16; k0++) {
        const int k = k0 * 8;
        uint32_t a0 = __float_as_uint(Xs[(rows0 + gid) * 132 + k + tig]);
        uint32_t a1 = __float_as_uint(Xs[(rows0 + gid + 8) * 132 + k + tig]);
        uint32_t a2 = __float_as_uint(Xs[(rows0 + gid) * 132 + k + tig + 4]);
        uint32_t a3 = __float_as_uint(Xs[(rows0 + gid + 8) * 132 + k + tig + 4]);
        #pragma unroll
        for (int nf = 0; nf < 4; nf++) {
            int n = cols0 + nf * 8 + gid;
            uint32_t b0 = __float_as_uint(Ws[(k + tig) * 72 + n]);
            uint32_t b1 = __float_as_uint(Ws[(k + tig + 4) * 72 + n]);
            mma_tf32(c[nf], a0, a1, a2, a3, b0, b1);
        }
    }
    // write fp32
    #pragma unroll
    for (int nf = 0; nf < 4; nf++) {
        int n = cols0 + nf * 8 + 2 * tig;
        int r0 = row0 + rows0 + gid, r1 = r0 + 8;
        if (r0 < M) {
            g_hW[(size_t)r0 * DIM + n]     = c[nf][0];
            g_hW[(size_t)r0 * DIM + n + 1] = c[nf][1];
        }
        if (r1 < M) {
            g_hW[(size_t)r1 * DIM + n]     = c[nf][2];
            g_hW[(size_t)r1 * DIM + n + 1] = c[nf][3];
        }
    }
}

// ---------------------------------------------------------------------------
// Node MLP (affine+ReLU, GEMM1+bias+ReLU, GEMM2 | pooling) on tf32 mma.
template <bool NEXT>
__global__ __launch_bounds__(256) void node_kernel(
    const float* __restrict__ ba, const float* __restrict__ gam,
    const float* __restrict__ bet, const float* __restrict__ Wb,
    const float* __restrict__ bb, const float* __restrict__ Wn,
    const void* __restrict__ batchp, int M)
{
    extern __shared__ float sm[];
    float* zs  = sm;                 // 64 x 68 (z tf32, then h)
    float* Wbs = zs + 64 * 68;       // 64 x 72 tf32
    float* Wns = Wbs + 64 * 72;      // 64 x 72 tf32 (NEXT only)
    __shared__ float A[64], B[64], bbs[64];
    __shared__ int sbat[64];

    const int t = threadIdx.x;
    const int row0 = blockIdx.x * 64;

    if (t < 64) {
        float inv = rsqrtf(1.0f + 1e-5f);
        float a = gam[t] * inv;
        A[t] = a;
        B[t] = ba[t] * a + bet[t];
        bbs[t] = bb[t];
    }
    // load + convert weights to stride-72 tf32
    for (int i = t; i < 64 * 16; i += 256) {
        int k = i >> 4, q = i & 15;
        float4 v = *(const float4*)(Wb + k * 64 + q * 4);
        v.x = to_tf32(v.x); v.y = to_tf32(v.y); v.z = to_tf32(v.z); v.w = to_tf32(v.w);
        *(float4*)(Wbs + k * 72 + q * 4) = v;
        if (NEXT) {
            float4 u = *(const float4*)(Wn + k * 64 + q * 4);
            u.x = to_tf32(u.x); u.y = to_tf32(u.y); u.z = to_tf32(u.z); u.w = to_tf32(u.w);
            *(float4*)(Wns + k * 72 + q * 4) = u;
        }
    }
    __syncthreads();   // A/B ready

    // load acc tile, apply affine+relu, convert to tf32 -> zs
    for (int i = t; i < 64 * 16; i += 256) {
        int r = i >> 4, q = i & 15;
        int gr = row0 + r; if (gr >= M) gr = M - 1;
        float4 v = *(const float4*)(g_acc + (size_t)gr * DIM + q * 4);
        int cc = q * 4;
        v.x = to_tf32(fmaxf(v.x * A[cc + 0] + B[cc + 0], 0.0f));
        v.y = to_tf32(fmaxf(v.y * A[cc + 1] + B[cc + 1], 0.0f));
        v.z = to_tf32(fmaxf(v.z * A[cc + 2] + B[cc + 2], 0.0f));
        v.w = to_tf32(fmaxf(v.w * A[cc + 3] + B[cc + 3], 0.0f));
        *(float4*)(zs + r * 68 + cc) = v;
    }
    __syncthreads();

    const int w = t >> 5, lane = t & 31;
    const int gid = lane >> 2, tig = lane & 3;
    const int rows0 = (w >> 1) * 16;
    const int cols0 = (w & 1) * 32;

    // ---- GEMM1: h = relu(z @ Wb + bb) ----
    float c1[4][4] = {};
    #pragma unroll
    for (int k0 = 0; k0 < 8; k0++) {
        const int k = k0 * 8;
        uint32_t a0 = __float_as_uint(zs[(rows0 + gid) * 68 + k + tig]);
        uint32_t a1 = __float_as_uint(zs[(rows0 + gid + 8) * 68 + k + tig]);
        uint32_t a2 = __float_as_uint(zs[(rows0 + gid) * 68 + k + tig + 4]);
        uint32_t a3 = __float_as_uint(zs[(rows0 + gid + 8) * 68 + k + tig + 4]);
        #pragma unroll
        for (int nf = 0; nf < 4; nf++) {
            int n = cols0 + nf * 8 + gid;
            uint32_t b0 = __float_as_uint(Wbs[(k + tig) * 72 + n]);
            uint32_t b1 = __float_as_uint(Wbs[(k + tig + 4) * 72 + n]);
            mma_tf32(c1[nf], a0, a1, a2, a3, b0, b1);
        }
    }
    __syncthreads();   // all reads of z done
    // epilogue: bias + relu (+ tf32 if feeding GEMM2); overwrite zs with h
    #pragma unroll
    for (int nf = 0; nf < 4; nf++) {
        int n = cols0 + nf * 8 + 2 * tig;
        int r0 = rows0 + gid, r1 = r0 + 8;
        float h00 = fmaxf(c1[nf][0] + bbs[n],     0.0f);
        float h01 = fmaxf(c1[nf][1] + bbs[n + 1], 0.0f);
        float h10 = fmaxf(c1[nf][2] + bbs[n],     0.0f);
        float h11 = fmaxf(c1[nf][3] + bbs[n + 1], 0.0f);
        if (NEXT) { h00 = to_tf32(h00); h01 = to_tf32(h01); h10 = to_tf32(h10); h11 = to_tf32(h11); }
        *(float2*)(zs + r0 * 68 + n) = make_float2(h00, h01);
        *(float2*)(zs + r1 * 68 + n) = make_float2(h10, h11);
    }
    __syncthreads();   // h fully in smem

    if (NEXT) {
        // ---- GEMM2: hW' = h @ Wn -> g_hW ----
        float c2[4][4] = {};
        #pragma unroll
        for (int k0 = 0; k0 < 8; k0++) {
            const int k = k0 * 8;
            uint32_t a0 = __float_as_uint(zs[(rows0 + gid) * 68 + k + tig]);
            uint32_t a1 = __float_as_uint(zs[(rows0 + gid + 8) * 68 + k + tig]);
            uint32_t a2 = __float_as_uint(zs[(rows0 + gid) * 68 + k + tig + 4]);
            uint32_t a3 = __float_as_uint(zs[(rows0 + gid + 8) * 68 + k + tig + 4]);
            #pragma unroll
            for (int nf = 0; nf < 4; nf++) {
                int n = cols0 + nf * 8 + gid;
                uint32_t b0 = __float_as_uint(Wns[(k + tig) * 72 + n]);
                uint32_t b1 = __float_as_uint(Wns[(k + tig + 4) * 72 + n]);
                mma_tf32(c2[nf], a0, a1, a2, a3, b0, b1);
            }
        }
        #pragma unroll
        for (int nf = 0; nf < 4; nf++) {
            int n = cols0 + nf * 8 + 2 * tig;
            int r0 = row0 + rows0 + gid, r1 = r0 + 8;
            if (r0 < M) {
                g_hW[(size_t)r0 * DIM + n]     = c2[nf][0];
                g_hW[(size_t)r0 * DIM + n + 1] = c2[nf][1];
            }
            if (r1 < M) {
                g_hW[(size_t)r1 * DIM + n]     = c2[nf][2];
                g_hW[(size_t)r1 * DIM + n + 1] = c2[nf][3];
            }
        }
    } else {
        // ---- pooling (batch sorted): run-length reduce per column ----
        if (t < 64) {
            int gr = row0 + t;
            int b = -1;
            if (gr < M) {
                if (g_is64) b = (int)((const long long*)batchp)[gr];
                else        b = ((const int*)batchp)[gr];
            }
            sbat[t] = b;
        }
        __syncthreads();
        if (t < 64) {
            const int c = t;
            float s = 0.0f;
            int cur = sbat[0];
            for (int r = 0; r < 64; r++) {
                int b = sbat[r];
                if (b < 0) break;
                if (b != cur) {
                    atomicAdd(&g_pool[cur * DIM + c], s);
                    s = 0.0f; cur = b;
                }
                s += zs[r * 68 + c];
            }
            if (cur >= 0) atomicAdd(&g_pool[cur * DIM + c], s);
        }
    }
}

// ---------------------------------------------------------------------------
__global__ __launch_bounds__(256) void cls_kernel(
    const float* __restrict__ Wl1, const float* __restrict__ bl1,
    const float* __restrict__ Wl2, const float* __restrict__ bl2,
    float* __restrict__ out)
{
    extern __shared__ float sm[];
    float* ps  = sm;             // 64 x 64 pooled
    float* Ws1 = ps + 4096;      // 64 x 64 summed Wl1
    float* z1  = Ws1 + 4096;     // 64 x 65
    const int t = threadIdx.x;

    for (int i = t; i < 4096; i += 256) {
        ps[i]  = g_pool[i];
        Ws1[i] = Wl1[i] + Wl1[4096 + i] + Wl1[8192 + i];
    }
    __syncthreads();

    const int c = t & 63;
    const int gbase = (t >> 6) * 16;
    for (int gg = 0; gg < 16; gg++) {
        int g = gbase + gg;
        float s = bl1[c];
        #pragma unroll 8
        for (int k = 0; k < 64; k++) s += ps[g * 64 + k] * Ws1[k * 64 + c];
        z1[g * 65 + c] = fmaxf(s, 0.0f);
    }
    __syncthreads();

    if (t < 64) {
        const int g = t;
        float a = bl2[0], b = bl2[1];
        #pragma unroll 8
        for (int k = 0; k < 64; k++) {
            float v = z1[g * 65 + k];
            a += v * Wl2[k * 2 + 0];
            b += v * Wl2[k * 2 + 1];
        }
        float m = fmaxf(a, b);
        float l = m + logf(expf(a - m) + expf(b - m));
        out[2 * g + 0] = a - l;
        out[2 * g + 1] = b - l;
    }
}

// ---------------------------------------------------------------------------
extern "C" void kernel_launch(void* const* d_in, const int* in_sizes, int n_in,
                              void* d_out, int out_size)
{
    const float* x     = (const float*)d_in[0];
    const void*  eidx  = d_in[1];
    const void*  batch = d_in[2];
    const float* W0a   = (const float*)d_in[3];
    const float* b0a   = (const float*)d_in[4];
    const float* g0    = (const float*)d_in[5];
    const float* be0   = (const float*)d_in[6];
    const float* W0b   = (const float*)d_in[7];
    const float* b0b   = (const float*)d_in[8];
    const float* Wsa   = (const float*)d_in[9];
    const float* bsa   = (const float*)d_in[10];
    const float* gs    = (const float*)d_in[11];
    const float* bes   = (const float*)d_in[12];
    const float* Wsb   = (const float*)d_in[13];
    const float* bsb   = (const float*)d_in[14];
    const float* Wl1   = (const float*)d_in[15];
    const float* bl1   = (const float*)d_in[16];
    const float* Wl2   = (const float*)d_in[17];
    const float* bl2   = (const float*)d_in[18];

    const int M = in_sizes[0] / 128;
    const int E = in_sizes[1] / 2;
    const int nblk = (M + 63) / 64;
    const int eblk = (E + 255) / 256;
    const int sblk = (M + 1023) / 1024;
    const int gblk = (M * 32 + 255) / 256;

    const size_t smem_lin0 = (64 * 132 + 128 * 72) * sizeof(float);   // 70656
    const size_t smem_node = (64 * 68 + 64 * 72 * 2) * sizeof(float); // 54272
    const size_t smem_cls  = (4096 + 4096 + 64 * 65) * sizeof(float);

    cudaFuncSetAttribute(lin0_kernel, cudaFuncAttributeMaxDynamicSharedMemorySize, (int)smem_lin0);
    cudaFuncSetAttribute(node_kernel<true>, cudaFuncAttributeMaxDynamicSharedMemorySize, (int)smem_node);
    cudaFuncSetAttribute(node_kernel<false>, cudaFuncAttributeMaxDynamicSharedMemorySize, (int)smem_node);
    cudaFuncSetAttribute(cls_kernel, cudaFuncAttributeMaxDynamicSharedMemorySize, (int)smem_cls);

    detect_kernel<<<1, 32>>>((const int*)eidx);
    zero_kernel<<<64, 256>>>(M);

    // build dst-CSR once; reused by all 3 gathers
    hist_kernel<<<eblk, 256>>>(eidx, E);
    scan_local_kernel<<<sblk, 256>>>(M);
    scan_bsum_kernel<<<1, 32>>>(sblk);
    scan_add_kernel<<<(M + 256) / 256 + 1, 256>>>(M, E);
    reorder_kernel<<<eblk, 256>>>(eidx, E);

    lin0_kernel<<<nblk, 256, smem_lin0>>>(x, W0a, M);
    gather_kernel<<<gblk, 256>>>(M);
    node_kernel<true><<<nblk, 256, smem_node>>>(b0a, g0, be0, W0b, b0b, Wsa, nullptr, M);
    gather_kernel<<<gblk, 256>>>(M);
    node_kernel<true><<<nblk, 256, smem_node>>>(bsa, gs, bes, Wsb, bsb, Wsa + 4096, nullptr, M);
    gather_kernel<<<gblk, 256>>>(M);
    node_kernel<false><<<nblk, 256, smem_node>>>(bsa + 64, gs + 64, bes + 64,
                                                 Wsb + 4096, bsb + 64, nullptr, batch, M);
    cls_kernel<<<1, 256, smem_cls>>>(Wl1, bl1, Wl2, bl2, (float*)d_out);
}